// round 8
// baseline (speedup 1.0000x reference)
#include <cuda_runtime.h>
#include <cuda_bf16.h>

// Batched Bloch RK4. RHS is affine per batch element:
//   u' = -g u ;  [v w]' = [[-g,-Om],[Om,-2g]][v w] + [0,-2g]
// RK4 with step h on y'=Ay+b is EXACTLY y+ = M y + c (degree-4 Taylor).
//
// Two-phase time-split:
//   kernel1: sequential recurrence, 1 elem/thread. Hot loop is branch-free:
//            h preloaded 8-at-a-time via LDS.128, group-prechecked against a
//            2-slot propagator cache, steps = FSETP + 7 SEL + 7 FMA (no BSSY).
//   kernel2: NCHUNK time-chunks in parallel; each THREAD owns one output
//            float4 per step (spans 2 batch elements, simulated redundantly)
//            -> lane-contiguous STG.128. DRAM-write bound (~6.1 TB/s).

#ifndef TMAX
#define TMAX 2048
#endif

#define NCHUNK 16
#define MAXB   65536
__device__ float g_ckpt[(NCHUNK - 1) * MAXB * 3];

// ---------- templated prop (used by kernel2 + fallback) ----------
template <int N> struct Prop {
    float pu[N], m00[N], m01[N], m10[N], m11[N], c0[N], c1[N];
};

template <int N>
__device__ __forceinline__ void make_prop(float h, const float* Om, const float* g,
                                          Prop<N>& P)
{
    const float i6 = 1.f / 6.f, i24 = 1.f / 24.f;
#pragma unroll
    for (int j = 0; j < N; ++j) {
        float b00 = -g[j] * h, b01 = -Om[j] * h, b10 = Om[j] * h, b11 = -2.f * g[j] * h;
        float s00 = b00 * b00 + b01 * b10;
        float s01 = b00 * b01 + b01 * b11;
        float s10 = b10 * b00 + b11 * b10;
        float s11 = b10 * b01 + b11 * b11;
        float t00 = s00 * b00 + s01 * b10;
        float t01 = s00 * b01 + s01 * b11;
        float t10 = s10 * b00 + s11 * b10;
        float t11 = s10 * b01 + s11 * b11;
        float q00 = s00 * s00 + s01 * s10;
        float q01 = s00 * s01 + s01 * s11;
        float q10 = s10 * s00 + s11 * s10;
        float q11 = s10 * s01 + s11 * s11;
        P.m00[j] = 1.f + b00 + 0.5f * s00 + i6 * t00 + i24 * q00;
        P.m01[j] =       b01 + 0.5f * s01 + i6 * t01 + i24 * q01;
        P.m10[j] =       b10 + 0.5f * s10 + i6 * t10 + i24 * q10;
        P.m11[j] = 1.f + b11 + 0.5f * s11 + i6 * t11 + i24 * q11;
        float p01 = h * (0.5f * b01 + i6 * s01 + i24 * t01);
        float p11 = h * (1.f + 0.5f * b11 + i6 * s11 + i24 * t11);
        float nb = -2.f * g[j];
        P.c0[j] = p01 * nb;
        P.c1[j] = p11 * nb;
        float be = -g[j] * h;
        P.pu[j] = 1.f + be * (1.f + be * (0.5f + be * (i6 + be * i24)));
    }
}

template <int N>
__device__ __forceinline__ void apply_prop(const Prop<N>& P, float* u, float* v, float* w)
{
#pragma unroll
    for (int j = 0; j < N; ++j) {
        u[j] = P.pu[j] * u[j];
        float vn = fmaf(P.m00[j], v[j], fmaf(P.m01[j], w[j], P.c0[j]));
        float wn = fmaf(P.m10[j], v[j], fmaf(P.m11[j], w[j], P.c1[j]));
        v[j] = vn; w[j] = wn;
    }
}

template <int N> struct PropCache {
    Prop<N> P0, P1;
    float h0, h1;
    bool last0;
    __device__ __forceinline__ void init() {
        h0 = __int_as_float(0x7fc00000);
        h1 = __int_as_float(0x7fc00000);
        last0 = false;
    }
    __device__ __forceinline__ void step(float h, const float* Om, const float* g,
                                         float* u, float* v, float* w) {
        if (h == h0)       { apply_prop(P0, u, v, w); last0 = true;  }
        else if (h == h1)  { apply_prop(P1, u, v, w); last0 = false; }
        else if (!last0)   { make_prop(h, Om, g, P0); h0 = h;
                             apply_prop(P0, u, v, w); last0 = true;  }
        else               { make_prop(h, Om, g, P1); h1 = h;
                             apply_prop(P1, u, v, w); last0 = false; }
    }
};

// ---------------- Kernel 1: checkpoint states only (1 elem/thread) ---------
// s_h here is 0-based: s_h[i] = ts[i+1] - ts[i]  (h of global step i+1).
__global__ __launch_bounds__(128) void bloch_ckpt_kernel(
    const float* __restrict__ y0,
    const float* __restrict__ ts,
    const float* __restrict__ params,
    int B, int T, int L)
{
    __shared__ float s_h[TMAX];
    for (int i = threadIdx.x; i < T - 1; i += blockDim.x)
        s_h[i] = ts[i + 1] - ts[i];
    __syncthreads();

    int e = blockIdx.x * blockDim.x + threadIdx.x;
    if (e >= B) return;

    float u = y0[3 * e + 0], v = y0[3 * e + 1], w = y0[3 * e + 2];
    float Om[1] = {params[3 * e + 0]}, g[1] = {params[3 * e + 2]};

    PropCache<1> C;
    C.init();

    for (int c = 1; c < NCHUNK; ++c) {
        int s0 = (c - 1) * L;              // s_h index of chunk's first step
        if (s0 >= T - 1) break;
        int cnt = T - 1 - s0;
        if (cnt > L) cnt = L;

        if (cnt == 32 && (s0 & 3) == 0) {
            const float4* hp = (const float4*)&s_h[s0];
#pragma unroll 1
            for (int grp = 0; grp < 4; ++grp) {
                float4 ha = hp[2 * grp], hb = hp[2 * grp + 1];
                float hr[8] = {ha.x, ha.y, ha.z, ha.w, hb.x, hb.y, hb.z, hb.w};

                bool known = true;
#pragma unroll
                for (int k = 0; k < 8; ++k)
                    known = known && ((hr[k] == C.h0) || (hr[k] == C.h1));

                if (__builtin_expect(!known, 0)) {
                    // rare: refill cache with full LRU logic
#pragma unroll
                    for (int k = 0; k < 8; ++k) {
                        float uu[1] = {u}, vv[1] = {v}, ww[1] = {w};
                        C.step(hr[k], Om, g, uu, vv, ww);
                        u = uu[0]; v = vv[0]; w = ww[0];
                    }
                } else {
                    // hot: branch-free (FSETP + SELs + FMAs, no BSSY)
                    bool e0last = C.last0;
#pragma unroll
                    for (int k = 0; k < 8; ++k) {
                        bool s0h = (hr[k] == C.h0);
                        float pu  = s0h ? C.P0.pu[0]  : C.P1.pu[0];
                        float m00 = s0h ? C.P0.m00[0] : C.P1.m00[0];
                        float m01 = s0h ? C.P0.m01[0] : C.P1.m01[0];
                        float m10 = s0h ? C.P0.m10[0] : C.P1.m10[0];
                        float m11 = s0h ? C.P0.m11[0] : C.P1.m11[0];
                        float c0  = s0h ? C.P0.c0[0]  : C.P1.c0[0];
                        float c1  = s0h ? C.P0.c1[0]  : C.P1.c1[0];
                        u = pu * u;
                        float vn = fmaf(m00, v, fmaf(m01, w, c0));
                        float wn = fmaf(m10, v, fmaf(m11, w, c1));
                        v = vn; w = wn;
                        e0last = s0h;
                    }
                    C.last0 = e0last;
                }
            }
        } else {
            for (int s = s0; s < s0 + cnt; ++s) {
                float uu[1] = {u}, vv[1] = {v}, ww[1] = {w};
                C.step(s_h[s], Om, g, uu, vv, ww);
                u = uu[0]; v = vv[0]; w = ww[0];
            }
        }

        float* o = g_ckpt + (long long)(c - 1) * B * 3 + 3LL * e;
        __stcg(o + 0, u);
        __stcg(o + 1, v);
        __stcg(o + 2, w);
    }
}

// ------- Kernel 2: output pass, one float4 per thread per step -------------
// float4 f covers floats [4f,4f+4) = components of elements e,e+1 with
// e = (4f)/3, off = 4f-3e. Thread simulates both elements (redundant 1.5x).
// s_h here is 1-based: s_h[s] = ts[s] - ts[s-1].
__global__ __launch_bounds__(128) void bloch_out_kernel(
    const float* __restrict__ y0,
    const float* __restrict__ ts,
    const float* __restrict__ params,
    float* __restrict__ out,
    int B, int T, int L)
{
    __shared__ float s_h[TMAX];
    for (int i = threadIdx.x + 1; i < T; i += blockDim.x)
        s_h[i] = ts[i] - ts[i - 1];
    __syncthreads();

    int c = blockIdx.y;
    int f = blockIdx.x * blockDim.x + threadIdx.x;
    int F = (3 * B) / 4;                 // float4s per timestep row
    if (f >= F) return;

    int sc = 1 + c * L;                  // first step of this chunk
    if (sc >= T) return;
    int se = sc + L;
    if (se > T) se = T;

    int e   = (4 * f) / 3;
    int off = 4 * f - 3 * e;
    bool o1 = (off >= 1), o2 = (off == 2);

    const float* src = (c == 0) ? y0 : (g_ckpt + (long long)(c - 1) * B * 3);
    float u[2], v[2], w[2], Om[2], g[2];
    u[0] = src[3 * e + 0]; v[0] = src[3 * e + 1]; w[0] = src[3 * e + 2];
    u[1] = src[3 * e + 3]; v[1] = src[3 * e + 4]; w[1] = src[3 * e + 5];
    Om[0] = params[3 * e + 0]; g[0] = params[3 * e + 2];
    Om[1] = params[3 * e + 3]; g[1] = params[3 * e + 5];

    float4* orow = (float4*)out + (long long)(sc - 1) * F + f;

#define STORE_ROW()                                                          \
    do {                                                                     \
        float x0 = o1 ? (o2 ? w[0] : v[0]) : u[0];                           \
        float x1 = o1 ? (o2 ? u[1] : w[0]) : v[0];                           \
        float x2 = o1 ? (o2 ? v[1] : u[1]) : w[0];                           \
        float x3 = o1 ? (o2 ? w[1] : v[1]) : u[1];                           \
        __stcs(orow, make_float4(x0, x1, x2, x3));                           \
    } while (0)

    if (c == 0) STORE_ROW();

    PropCache<2> C;
    C.init();

    if (se - sc == 32) {
#pragma unroll 4
        for (int k = 0; k < 32; ++k) {
            C.step(s_h[sc + k], Om, g, u, v, w);
            orow += F;
            STORE_ROW();
        }
    } else {
        for (int s = sc; s < se; ++s) {
            C.step(s_h[s], Om, g, u, v, w);
            orow += F;
            STORE_ROW();
        }
    }
#undef STORE_ROW
}

// ---------------- scalar fallback (any B, any T) ---------------------------
__global__ __launch_bounds__(256) void bloch_rk4_scalar(
    const float* __restrict__ y0,
    const float* __restrict__ ts,
    const float* __restrict__ params,
    float* __restrict__ out,
    int B, int T)
{
    int b = blockIdx.x * blockDim.x + threadIdx.x;
    if (b >= B) return;

    float u[1] = {y0[3 * b + 0]}, v[1] = {y0[3 * b + 1]}, w[1] = {y0[3 * b + 2]};
    float Om[1] = {params[3 * b + 0]}, g[1] = {params[3 * b + 2]};

    const long long B3 = 3LL * B;
    float* o = out + 3LL * b;
    o[0] = u[0]; o[1] = v[0]; o[2] = w[0];

    PropCache<1> C;
    C.init();
    float ts_prev = ts[0];

    for (int t = 1; t < T; ++t) {
        float ts_cur = __ldg(ts + t);
        float h = ts_cur - ts_prev;
        ts_prev = ts_cur;
        C.step(h, Om, g, u, v, w);
        o += B3;
        o[0] = u[0]; o[1] = v[0]; o[2] = w[0];
    }
}

extern "C" void kernel_launch(void* const* d_in, const int* in_sizes, int n_in,
                              void* d_out, int out_size) {
    const float* y0     = (const float*)d_in[0];   // (B,3)
    const float* ts     = (const float*)d_in[1];   // (T,)
    const float* params = (const float*)d_in[2];   // (B,3)
    float* out = (float*)d_out;                    // (T,B,3)

    int B = in_sizes[0] / 3;
    int T = in_sizes[1];

    if ((B & 3) == 0 && B <= MAXB && T >= 2 && T <= TMAX) {
        int L = (T - 1 + NCHUNK - 1) / NCHUNK;     // steps per chunk

        int tpb1 = 128;
        bloch_ckpt_kernel<<<(B + tpb1 - 1) / tpb1, tpb1>>>(y0, ts, params, B, T, L);

        int F = (3 * B) / 4;
        int tpb2 = 128;
        dim3 grid2((F + tpb2 - 1) / tpb2, NCHUNK);
        bloch_out_kernel<<<grid2, tpb2>>>(y0, ts, params, out, B, T, L);
    } else {
        int tpb = 256;
        bloch_rk4_scalar<<<(B + tpb - 1) / tpb, tpb>>>(y0, ts, params, out, B, T);
    }
}